// round 4
// baseline (speedup 1.0000x reference)
#include <cuda_runtime.h>
#include <cuda_fp16.h>
#include <cstdint>

namespace {
constexpr int NTOK = 16384;
constexpr int DDIM = 2048;
constexpr int RDIM = 256;

constexpr int BM = 128;   // rows per CTA
constexpr int BN = 256;   // cols per phase-1 tile / per phase-2 chunk
constexpr int BK = 32;
constexpr int S  = 4;     // pipeline stages
constexpr int SA = BK + 8;    // 40 halves  (80 B rows)
constexpr int SB = BN + 8;    // 264 halves (528 B rows)
constexpr int SH = BN + 8;    // h row stride
constexpr int A_STAGE = BM * SA;   // halves
constexpr int B_STAGE = BK * SB;   // halves
constexpr int NITER1 = DDIM / BK;          // 64 phase-1 iters
constexpr int NCHUNK = DDIM / BN;          // 8 phase-2 chunks
constexpr int KT2    = RDIM / BK;          // 8 iters per chunk
constexpr int NITER  = NITER1 + NCHUNK * KT2;  // 128

// smem byte offsets
constexpr int OFF_A  = 0;                          // 40960
constexpr int OFF_B  = OFF_A + S * A_STAGE * 2;    // 67584
constexpr int OFF_H  = OFF_B + S * B_STAGE * 2;    // 67584
constexpr int OFF_B1 = OFF_H + BM * SH * 2;        // 1024
constexpr int OFF_B2 = OFF_B1 + 256 * 4;           // 8192
constexpr int OFF_MB = OFF_B2 + 2048 * 4;          // 64
constexpr int SMEM_TOTAL = OFF_MB + 64;            // 185408
}

// Scratch (__device__ globals; no allocation allowed)
__device__ __align__(16) __half g_win[(size_t)DDIM * RDIM];   // W_in fp16 [K=D, M=R]
__device__ __align__(16) __half g_wout[(size_t)RDIM * DDIM];  // W_out fp16 [K=R, M=D]

__device__ __forceinline__ uint32_t smem_u32(const void* p) {
    return (uint32_t)__cvta_generic_to_shared(p);
}
__device__ __forceinline__ void cp_async16(uint32_t dst, const void* src) {
    asm volatile("cp.async.cg.shared.global [%0], [%1], 16;\n" :: "r"(dst), "l"(src));
}
__device__ __forceinline__ void cp_commit() { asm volatile("cp.async.commit_group;\n" ::: "memory"); }
template <int N>
__device__ __forceinline__ void cp_wait() {
    asm volatile("cp.async.wait_group %0;\n" :: "n"(N) : "memory");
}
__device__ __forceinline__ void mbar_init(uint32_t a, uint32_t cnt) {
    asm volatile("mbarrier.init.shared.b64 [%0], %1;" :: "r"(a), "r"(cnt) : "memory");
}
__device__ __forceinline__ void mbar_arrive(uint32_t a) {
    asm volatile("mbarrier.arrive.release.cta.shared::cta.b64 _, [%0];" :: "r"(a) : "memory");
}
__device__ __forceinline__ void mbar_wait(uint32_t a, uint32_t parity) {
    asm volatile(
        "{\n\t.reg .pred P;\n"
        "LAB_W%=:\n\t"
        "mbarrier.try_wait.parity.acquire.cta.shared::cta.b64 P, [%0], %1, 0x989680;\n\t"
        "@P bra LAB_D%=;\n\t"
        "bra LAB_W%=;\n"
        "LAB_D%=:\n\t}"
        :: "r"(a), "r"(parity) : "memory");
}
__device__ __forceinline__ void ldsm_x4(uint32_t addr, uint32_t& r0, uint32_t& r1,
                                        uint32_t& r2, uint32_t& r3) {
    asm volatile("ldmatrix.sync.aligned.m8n8.x4.shared.b16 {%0,%1,%2,%3}, [%4];\n"
                 : "=r"(r0), "=r"(r1), "=r"(r2), "=r"(r3) : "r"(addr));
}
__device__ __forceinline__ void ldsm_x4_t(uint32_t addr, uint32_t& r0, uint32_t& r1,
                                          uint32_t& r2, uint32_t& r3) {
    asm volatile("ldmatrix.sync.aligned.m8n8.x4.trans.shared.b16 {%0,%1,%2,%3}, [%4];\n"
                 : "=r"(r0), "=r"(r1), "=r"(r2), "=r"(r3) : "r"(addr));
}
__device__ __forceinline__ void mma16816(float* c, const uint32_t* a, uint32_t b0, uint32_t b1) {
    asm volatile(
        "mma.sync.aligned.m16n8k16.row.col.f32.f16.f16.f32 "
        "{%0,%1,%2,%3}, {%4,%5,%6,%7}, {%8,%9}, {%0,%1,%2,%3};\n"
        : "+f"(c[0]), "+f"(c[1]), "+f"(c[2]), "+f"(c[3])
        : "r"(a[0]), "r"(a[1]), "r"(a[2]), "r"(a[3]), "r"(b0), "r"(b1));
}

// ---------------------------------------------------------------------------
// Weight prep: 2:4 soft-threshold along last dim, * scale, cast fp16.
// ---------------------------------------------------------------------------
template <int WHICH>
__global__ void prep_weight_kernel(const float* __restrict__ w,
                                   const float* __restrict__ scale) {
    constexpr int ngroups = (DDIM * RDIM) / 4;
    int g = blockIdx.x * blockDim.x + threadIdx.x;
    if (g >= ngroups) return;
    float4 v = reinterpret_cast<const float4*>(w)[g];
    float s = scale[0];
    float a0 = fabsf(v.x), a1 = fabsf(v.y), a2 = fabsf(v.z), a3 = fabsf(v.w);
    float lo1 = fminf(a0, a1), hi1 = fmaxf(a0, a1);
    float lo2 = fminf(a2, a3), hi2 = fmaxf(a2, a3);
    float t = fminf(fmaxf(lo1, lo2), fminf(hi1, hi2));  // 2nd smallest of 4
    float r0 = copysignf(fmaxf(a0 - t, 0.0f), v.x) * s;
    float r1 = copysignf(fmaxf(a1 - t, 0.0f), v.y) * s;
    float r2 = copysignf(fmaxf(a2 - t, 0.0f), v.z) * s;
    float r3 = copysignf(fmaxf(a3 - t, 0.0f), v.w) * s;
    __half2 h01 = __floats2half2_rn(r0, r1);
    __half2 h23 = __floats2half2_rn(r2, r3);
    uint2 pk;
    pk.x = *reinterpret_cast<uint32_t*>(&h01);
    pk.y = *reinterpret_cast<uint32_t*>(&h23);
    __half* out = (WHICH == 0) ? g_win : g_wout;
    reinterpret_cast<uint2*>(out)[g] = pk;
}

// ---------------------------------------------------------------------------
// Fused persistent kernel (see header comment in theory above).
// ---------------------------------------------------------------------------
__global__ __launch_bounds__(320, 1)
void fused_kernel(const float* __restrict__ x, const float* __restrict__ b_in,
                  const float* __restrict__ b_out, float* __restrict__ y) {
    extern __shared__ char sm[];
    const uint32_t smA  = smem_u32(sm + OFF_A);
    const uint32_t smB  = smem_u32(sm + OFF_B);
    const uint32_t smH  = smem_u32(sm + OFF_H);
    float* b1S = reinterpret_cast<float*>(sm + OFF_B1);
    float* b2S = reinterpret_cast<float*>(sm + OFF_B2);
    const uint32_t mbF = smem_u32(sm + OFF_MB);        // full[4]
    const uint32_t mbE = mbF + 32;                     // empty[4]

    const int tid = threadIdx.x;
    const int bm  = blockIdx.x * BM;

    if (tid == 0) {
#pragma unroll
        for (int s = 0; s < S; ++s) { mbar_init(mbF + s * 8, 2); mbar_init(mbE + s * 8, 8); }
    }
    for (int i = tid; i < 256; i += 320) b1S[i] = b_in[i];
    for (int i = tid; i < 2048; i += 320) b2S[i] = b_out[i];
    __syncthreads();

    if (tid < 256) {
        // ================= COMPUTE WARPS =================
        const int lane = tid & 31;
        const int wid  = tid >> 5;
        const int wm   = wid & 1;
        const int wn   = wid >> 1;
        const int arow = wm * 64 + (lane & 15);
        const int asel = (lane >> 4) * 8;
        const int brow = (lane & 15);
        const int bsel = (lane >> 4) * 8;

        float acc[4][8][4];
#pragma unroll
        for (int i = 0; i < 4; ++i)
#pragma unroll
            for (int j = 0; j < 8; ++j)
#pragma unroll
                for (int k = 0; k < 4; ++k) acc[i][j][k] = 0.0f;

#pragma unroll 1
        for (int j = 0; j < NITER; ++j) {
            const int s = j & 3;
            const int u = j >> 2;
            mbar_wait(mbF + s * 8, u & 1);

            uint32_t abase;
            int astr;
            if (j < NITER1) { abase = smA + s * A_STAGE * 2; astr = SA; }
            else            { abase = smH + ((j - NITER1) & 7) * BK * 2; astr = SH; }
            const uint32_t bbase = smB + s * B_STAGE * 2;

#pragma unroll
            for (int ks = 0; ks < 2; ++ks) {
                const int k0 = ks * 16;
                uint32_t afr[4][4];
#pragma unroll
                for (int mi = 0; mi < 4; ++mi)
                    ldsm_x4(abase + ((arow + mi * 16) * astr + k0 + asel) * 2,
                            afr[mi][0], afr[mi][1], afr[mi][2], afr[mi][3]);
#pragma unroll
                for (int np = 0; np < 4; ++np) {
                    uint32_t b0, b1, b2, b3;
                    ldsm_x4_t(bbase + ((k0 + brow) * SB + wn * 64 + np * 16 + bsel) * 2,
                              b0, b1, b2, b3);
#pragma unroll
                    for (int mi = 0; mi < 4; ++mi) {
                        mma16816(acc[mi][np * 2],     afr[mi], b0, b1);
                        mma16816(acc[mi][np * 2 + 1], afr[mi], b2, b3);
                    }
                }
            }
            __syncwarp();
            if (lane == 0) mbar_arrive(mbE + s * 8);

            if (j == NITER1 - 1) {
                // ---- phase handoff: h = fp16(acc + b1) -> smem ----
#pragma unroll
                for (int mi = 0; mi < 4; ++mi)
#pragma unroll
                    for (int ni = 0; ni < 8; ++ni) {
                        const int r = wm * 64 + mi * 16 + (lane >> 2);
                        const int c = wn * 64 + ni * 8 + (lane & 3) * 2;
                        const float bb0 = b1S[c], bb1 = b1S[c + 1];
                        __half2 v0 = __floats2half2_rn(acc[mi][ni][0] + bb0,
                                                       acc[mi][ni][1] + bb1);
                        __half2 v1 = __floats2half2_rn(acc[mi][ni][2] + bb0,
                                                       acc[mi][ni][3] + bb1);
                        asm volatile("st.shared.b32 [%0], %1;" ::
                            "r"(smH + (r * SH + c) * 2), "r"(*(uint32_t*)&v0) : "memory");
                        asm volatile("st.shared.b32 [%0], %1;" ::
                            "r"(smH + ((r + 8) * SH + c) * 2), "r"(*(uint32_t*)&v1) : "memory");
                    }
                asm volatile("bar.sync 1, 256;" ::: "memory");
#pragma unroll
                for (int mi = 0; mi < 4; ++mi)
#pragma unroll
                    for (int ni = 0; ni < 8; ++ni)
#pragma unroll
                        for (int k = 0; k < 4; ++k) acc[mi][ni][k] = 0.0f;
            } else if (j >= NITER1 && ((j - NITER1) & 7) == 7) {
                // ---- chunk epilogue: y chunk = acc + b2 ----
                const int ch = (j - NITER1) >> 3;
#pragma unroll
                for (int mi = 0; mi < 4; ++mi)
#pragma unroll
                    for (int ni = 0; ni < 8; ++ni) {
                        const int r  = bm + wm * 64 + mi * 16 + (lane >> 2);
                        const int lc = wn * 64 + ni * 8 + (lane & 3) * 2;
                        const int gc = ch * 256 + lc;
                        const float bb0 = b2S[gc], bb1 = b2S[gc + 1];
                        *reinterpret_cast<float2*>(&y[(size_t)r * DDIM + gc]) =
                            make_float2(acc[mi][ni][0] + bb0, acc[mi][ni][1] + bb1);
                        *reinterpret_cast<float2*>(&y[(size_t)(r + 8) * DDIM + gc]) =
                            make_float2(acc[mi][ni][2] + bb0, acc[mi][ni][3] + bb1);
#pragma unroll
                        for (int k = 0; k < 4; ++k) acc[mi][ni][k] = 0.0f;
                    }
            }
        }
    } else {
        // ================= PRODUCER WARPS =================
        const int ptid  = tid - 256;   // 0..63
        const int plane = tid & 31;

        float4 abuf[2][16];
        {
            const float4* s0 = reinterpret_cast<const float4*>(
                x + (size_t)(bm + 2 * ptid) * DDIM);
            const float4* s1 = reinterpret_cast<const float4*>(
                x + (size_t)(bm + 2 * ptid + 1) * DDIM);
#pragma unroll
            for (int i = 0; i < 8; ++i) { abuf[0][i] = s0[i]; abuf[0][8 + i] = s1[i]; }
        }

#pragma unroll 1
        for (int j = 0; j < NITER; ++j) {
            const int s = j & 3;
            const int u = j >> 2;
            if (u >= 1) mbar_wait(mbE + s * 8, (u - 1) & 1);

            // ---- B tile: 32 rows x 256 halves via cp.async ----
            const __half* Bg;
            size_t mstr;
            if (j < NITER1) { Bg = g_win + (size_t)j * BK * RDIM; mstr = RDIM; }
            else {
                const int jj = j - NITER1;
                Bg = g_wout + (size_t)(jj & 7) * BK * DDIM + (size_t)(jj >> 3) * 256;
                mstr = DDIM;
            }
#pragma unroll
            for (int i = 0; i < 16; ++i) {
                const int c = i * 64 + ptid;
                const int row = c >> 5, col = (c & 31) * 8;
                cp_async16(smB + s * B_STAGE * 2 + (row * SB + col) * 2,
                           Bg + (size_t)row * mstr + col);
            }
            cp_commit();

            if (j < NITER1) {
                if (j + 1 < NITER1) {
                    const float4* s0 = reinterpret_cast<const float4*>(
                        x + (size_t)(bm + 2 * ptid) * DDIM + (j + 1) * BK);
                    const float4* s1 = reinterpret_cast<const float4*>(
                        x + (size_t)(bm + 2 * ptid + 1) * DDIM + (j + 1) * BK);
                    const int nb = (j + 1) & 1;
#pragma unroll
                    for (int i = 0; i < 8; ++i) { abuf[nb][i] = s0[i]; abuf[nb][8 + i] = s1[i]; }
                }
                // cvt + STS current buffer: 2 rows x 32 halves (4 x st.v4 each 16B)
                const int b = j & 1;
#pragma unroll
                for (int r = 0; r < 2; ++r) {
                    uint32_t o[16];
#pragma unroll
                    for (int i = 0; i < 8; ++i) {
                        float4 v = abuf[b][r * 8 + i];
                        __half2 h0 = __floats2half2_rn(v.x, v.y);
                        __half2 h1 = __floats2half2_rn(v.z, v.w);
                        o[i * 2]     = *reinterpret_cast<uint32_t*>(&h0);
                        o[i * 2 + 1] = *reinterpret_cast<uint32_t*>(&h1);
                    }
                    const uint32_t base = smA + s * A_STAGE * 2 + (2 * ptid + r) * SA * 2;
                    asm volatile("st.shared.v4.b32 [%0], {%1,%2,%3,%4};" ::
                        "r"(base),      "r"(o[0]),  "r"(o[1]),  "r"(o[2]),  "r"(o[3])  : "memory");
                    asm volatile("st.shared.v4.b32 [%0], {%1,%2,%3,%4};" ::
                        "r"(base + 16), "r"(o[4]),  "r"(o[5]),  "r"(o[6]),  "r"(o[7])  : "memory");
                    asm volatile("st.shared.v4.b32 [%0], {%1,%2,%3,%4};" ::
                        "r"(base + 32), "r"(o[8]),  "r"(o[9]),  "r"(o[10]), "r"(o[11]) : "memory");
                    asm volatile("st.shared.v4.b32 [%0], {%1,%2,%3,%4};" ::
                        "r"(base + 48), "r"(o[12]), "r"(o[13]), "r"(o[14]), "r"(o[15]) : "memory");
                }
            }

            cp_wait<3>();
            if (j >= 3) { __syncwarp(); if (plane == 0) mbar_arrive(mbF + ((j - 3) & 3) * 8); }
        }
        cp_wait<2>(); __syncwarp(); if (plane == 0) mbar_arrive(mbF + ((NITER - 3) & 3) * 8);
        cp_wait<1>(); __syncwarp(); if (plane == 0) mbar_arrive(mbF + ((NITER - 2) & 3) * 8);
        cp_wait<0>(); __syncwarp(); if (plane == 0) mbar_arrive(mbF + ((NITER - 1) & 3) * 8);
    }
}

// ---------------------------------------------------------------------------
// kernel_launch. inputs: x, weight_in, weight_out, bias_in, bias_out,
//                        sparse_scale_in, sparse_scale_out
// ---------------------------------------------------------------------------
extern "C" void kernel_launch(void* const* d_in, const int* in_sizes, int n_in,
                              void* d_out, int out_size) {
    const float* x     = (const float*)d_in[0];
    const float* w_in  = (const float*)d_in[1];
    const float* w_out = (const float*)d_in[2];
    const float* b_in  = (const float*)d_in[3];
    const float* b_out = (const float*)d_in[4];
    const float* s_in  = (const float*)d_in[5];
    const float* s_out = (const float*)d_in[6];
    float* y = (float*)d_out;

    constexpr int ngroups = (DDIM * RDIM) / 4;
    prep_weight_kernel<0><<<(ngroups + 255) / 256, 256>>>(w_in, s_in);
    prep_weight_kernel<1><<<(ngroups + 255) / 256, 256>>>(w_out, s_out);

    cudaFuncSetAttribute(fused_kernel, cudaFuncAttributeMaxDynamicSharedMemorySize, SMEM_TOTAL);
    fused_kernel<<<NTOK / BM, 320, SMEM_TOTAL>>>(x, b_in, b_out, y);
}

// round 6
// speedup vs baseline: 2.6619x; 2.6619x over previous
#include <cuda_runtime.h>
#include <cuda_fp16.h>
#include <cstdint>

namespace {
constexpr int NTOK = 16384;
constexpr int DDIM = 2048;
constexpr int RDIM = 256;
}

// Scratch (__device__ globals; no allocation allowed)
__device__ __align__(16) __half g_win[(size_t)DDIM * RDIM];   // W_in fp16 [K=D, M=R]
__device__ __align__(16) __half g_wout[(size_t)RDIM * DDIM];  // W_out fp16 [K=R, M=D]
__device__ __align__(16) __half g_h[(size_t)NTOK * RDIM];     // hidden fp16 [N, R]

__device__ __forceinline__ uint32_t smem_u32(const void* p) {
    return (uint32_t)__cvta_generic_to_shared(p);
}
__device__ __forceinline__ void cp_async16(uint32_t dst, const void* src) {
    asm volatile("cp.async.cg.shared.global [%0], [%1], 16;\n" :: "r"(dst), "l"(src));
}
__device__ __forceinline__ void cp_commit() { asm volatile("cp.async.commit_group;\n" ::: "memory"); }
template <int N>
__device__ __forceinline__ void cp_wait() {
    asm volatile("cp.async.wait_group %0;\n" :: "n"(N) : "memory");
}
__device__ __forceinline__ void ldsm_x4(uint32_t addr, uint32_t& r0, uint32_t& r1,
                                        uint32_t& r2, uint32_t& r3) {
    asm volatile("ldmatrix.sync.aligned.m8n8.x4.shared.b16 {%0,%1,%2,%3}, [%4];\n"
                 : "=r"(r0), "=r"(r1), "=r"(r2), "=r"(r3) : "r"(addr));
}
__device__ __forceinline__ void ldsm_x4_t(uint32_t addr, uint32_t& r0, uint32_t& r1,
                                          uint32_t& r2, uint32_t& r3) {
    asm volatile("ldmatrix.sync.aligned.m8n8.x4.trans.shared.b16 {%0,%1,%2,%3}, [%4];\n"
                 : "=r"(r0), "=r"(r1), "=r"(r2), "=r"(r3) : "r"(addr));
}
__device__ __forceinline__ void mma16816(float* c, const uint32_t* a, uint32_t b0, uint32_t b1) {
    asm volatile(
        "mma.sync.aligned.m16n8k16.row.col.f32.f16.f16.f32 "
        "{%0,%1,%2,%3}, {%4,%5,%6,%7}, {%8,%9}, {%0,%1,%2,%3};\n"
        : "+f"(c[0]), "+f"(c[1]), "+f"(c[2]), "+f"(c[3])
        : "r"(a[0]), "r"(a[1]), "r"(a[2]), "r"(a[3]), "r"(b0), "r"(b1));
}

// ---------------------------------------------------------------------------
// Combined weight prep: 2:4 soft-threshold along last dim, * scale, cast fp16.
// First half of grid handles W_in -> g_win, second half W_out -> g_wout.
// ---------------------------------------------------------------------------
__global__ void prep_both_kernel(const float* __restrict__ w_in,
                                 const float* __restrict__ s_in,
                                 const float* __restrict__ w_out,
                                 const float* __restrict__ s_out) {
    constexpr int ngroups = (DDIM * RDIM) / 4;   // 131072
    int g = blockIdx.x * blockDim.x + threadIdx.x;
    const float* w;
    const float* sc;
    __half* out;
    int gi;
    if (g < ngroups) { w = w_in; sc = s_in; out = g_win; gi = g; }
    else             { w = w_out; sc = s_out; out = g_wout; gi = g - ngroups; }
    float4 v = reinterpret_cast<const float4*>(w)[gi];
    float s = sc[0];
    float a0 = fabsf(v.x), a1 = fabsf(v.y), a2 = fabsf(v.z), a3 = fabsf(v.w);
    float lo1 = fminf(a0, a1), hi1 = fmaxf(a0, a1);
    float lo2 = fminf(a2, a3), hi2 = fmaxf(a2, a3);
    float t = fminf(fmaxf(lo1, lo2), fminf(hi1, hi2));  // 2nd smallest of 4
    float r0 = copysignf(fmaxf(a0 - t, 0.0f), v.x) * s;
    float r1 = copysignf(fmaxf(a1 - t, 0.0f), v.y) * s;
    float r2 = copysignf(fmaxf(a2 - t, 0.0f), v.z) * s;
    float r3 = copysignf(fmaxf(a3 - t, 0.0f), v.w) * s;
    __half2 h01 = __floats2half2_rn(r0, r1);
    __half2 h23 = __floats2half2_rn(r2, r3);
    uint2 pk;
    pk.x = *reinterpret_cast<uint32_t*>(&h01);
    pk.y = *reinterpret_cast<uint32_t*>(&h23);
    reinterpret_cast<uint2*>(out)[gi] = pk;
}

// ---------------------------------------------------------------------------
// GEMM 0: h[N,256] = fp16(x[N,2048] @ W_in + b_in).  x converted on the fly.
// CTA 128x256xBK32, 8 warps 2(M)x4(N) of 64x64 tiles, 3-stage cp.async for B,
// A path: LDG fp32 (pre-issued) -> cvt -> STS fp16.  (R3 config, measured ~68us)
// ---------------------------------------------------------------------------
__global__ __launch_bounds__(256, 1)
void gemm0_kernel(const float* __restrict__ x, const float* __restrict__ bias) {
    constexpr int K  = DDIM;
    constexpr int M  = RDIM;
    constexpr int BM = 128, BN = 256, BK = 32;
    constexpr int S  = 3;
    constexpr int KT = K / BK;
    constexpr int SA = BK + 8;    // 40
    constexpr int SB = BN + 8;    // 264
    constexpr int A_STAGE = BM * SA;
    constexpr int B_STAGE = BK * SB;

    extern __shared__ char dynsm[];
    __half* As   = reinterpret_cast<__half*>(dynsm);
    __half* Bs   = As + S * A_STAGE;
    float* biasS = reinterpret_cast<float*>(Bs + S * B_STAGE);

    const int tid  = threadIdx.x;
    const int lane = tid & 31;
    const int wid  = tid >> 5;
    const int wm   = wid & 1;
    const int wn   = wid >> 1;
    const int bm   = blockIdx.y * BM;

    if (tid < BN) biasS[tid] = bias[tid];

    float acc[4][8][4];
#pragma unroll
    for (int i = 0; i < 4; ++i)
#pragma unroll
        for (int j = 0; j < 8; ++j)
#pragma unroll
            for (int k = 0; k < 4; ++k) acc[i][j][k] = 0.0f;

    auto loadB = [&](int kt, int s) {
        const __half* Bg = g_win + (size_t)(kt * BK) * M;
#pragma unroll
        for (int p = 0; p < 4; ++p) {
            int c = tid + p * 256;
            int row = c >> 5, col = (c & 31) * 8;
            cp_async16(smem_u32(&Bs[s * B_STAGE + row * SB + col]),
                       Bg + (size_t)row * M + col);
        }
    };

    float4 a32[4];
    auto ldgA = [&](int kt) {
        const float* Ag = x + (size_t)(bm + (tid >> 1)) * K + kt * BK + (tid & 1) * 16;
#pragma unroll
        for (int p = 0; p < 4; ++p)
            a32[p] = reinterpret_cast<const float4*>(Ag)[p];
    };
    auto stsA = [&](int s) {
        __half h[16];
#pragma unroll
        for (int p = 0; p < 4; ++p) {
            h[p * 4 + 0] = __float2half_rn(a32[p].x);
            h[p * 4 + 1] = __float2half_rn(a32[p].y);
            h[p * 4 + 2] = __float2half_rn(a32[p].z);
            h[p * 4 + 3] = __float2half_rn(a32[p].w);
        }
        int row = tid >> 1, col = (tid & 1) * 16;
        *reinterpret_cast<uint4*>(&As[s * A_STAGE + row * SA + col]) =
            *reinterpret_cast<uint4*>(&h[0]);
        *reinterpret_cast<uint4*>(&As[s * A_STAGE + row * SA + col + 8]) =
            *reinterpret_cast<uint4*>(&h[8]);
    };

#pragma unroll
    for (int s = 0; s < S; ++s) {
        ldgA(s);
        stsA(s);
        loadB(s, s);
        cp_commit();
    }

    for (int kt = 0; kt < KT; ++kt) {
        const int s = kt % S;
        const bool more = (kt + S < KT);
        cp_wait<S - 1>();
        __syncthreads();

        if (more) ldgA(kt + S);

#pragma unroll
        for (int ks = 0; ks < 2; ++ks) {
            const int k0 = ks * 16;
            uint32_t afr[4][4];
#pragma unroll
            for (int mi = 0; mi < 4; ++mi) {
                uint32_t addr = smem_u32(
                    &As[s * A_STAGE + (wm * 64 + mi * 16 + (lane & 15)) * SA + k0 + (lane >> 4) * 8]);
                ldsm_x4(addr, afr[mi][0], afr[mi][1], afr[mi][2], afr[mi][3]);
            }
#pragma unroll
            for (int np = 0; np < 4; ++np) {
                uint32_t b0, b1, b2, b3;
                uint32_t addr = smem_u32(
                    &Bs[s * B_STAGE + (k0 + (lane & 15)) * SB + wn * 64 + np * 16 + (lane >> 4) * 8]);
                ldsm_x4_t(addr, b0, b1, b2, b3);
#pragma unroll
                for (int mi = 0; mi < 4; ++mi) {
                    mma16816(acc[mi][np * 2],     afr[mi], b0, b1);
                    mma16816(acc[mi][np * 2 + 1], afr[mi], b2, b3);
                }
            }
        }

        __syncthreads();
        if (more) { stsA(s); loadB(kt + S, s); }
        cp_commit();
    }

    // epilogue -> g_h fp16
    const int row0 = bm + wm * 64;
    const int col0 = wn * 64;
#pragma unroll
    for (int mi = 0; mi < 4; ++mi) {
#pragma unroll
        for (int ni = 0; ni < 8; ++ni) {
            const int r = row0 + mi * 16 + (lane >> 2);
            const int c = col0 + ni * 8 + (lane & 3) * 2;
            const float bb0 = biasS[c];
            const float bb1 = biasS[c + 1];
            __half2* H = reinterpret_cast<__half2*>(g_h);
            H[((size_t)r * M + c) >> 1] =
                __floats2half2_rn(acc[mi][ni][0] + bb0, acc[mi][ni][1] + bb1);
            H[((size_t)(r + 8) * M + c) >> 1] =
                __floats2half2_rn(acc[mi][ni][2] + bb0, acc[mi][ni][3] + bb1);
        }
    }
}

// ---------------------------------------------------------------------------
// GEMM 1: y[N,2048] = h[N,256] @ W_out + b_out (fp32 out).
// Small CTAs: 128 threads (4 warps, 2x2 of 64x64 tiles), BM128/BN128/BK32,
// 3-stage cp.async, 2 CTAs/SM -> independent CTAs overlap prologue/epilogue.
// ---------------------------------------------------------------------------
__global__ __launch_bounds__(128, 2)
void gemm1_kernel(const float* __restrict__ bias, float* __restrict__ y) {
    constexpr int K  = RDIM;
    constexpr int M  = DDIM;
    constexpr int BM = 128, BN = 128, BK = 32;
    constexpr int S  = 3;
    constexpr int KT = K / BK;    // 8
    constexpr int SA = BK + 8;    // 40
    constexpr int SB = BN + 8;    // 136
    constexpr int A_STAGE = BM * SA;
    constexpr int B_STAGE = BK * SB;

    extern __shared__ char dynsm[];
    __half* As   = reinterpret_cast<__half*>(dynsm);
    __half* Bs   = As + S * A_STAGE;
    float* biasS = reinterpret_cast<float*>(Bs + S * B_STAGE);

    const int tid  = threadIdx.x;
    const int lane = tid & 31;
    const int wid  = tid >> 5;
    const int wm   = wid & 1;          // 0..1
    const int wn   = wid >> 1;         // 0..1
    const int bm   = blockIdx.y * BM;
    const int bn   = blockIdx.x * BN;

    biasS[tid] = bias[bn + tid];       // 128 threads, 128 cols

    float acc[4][8][4];
#pragma unroll
    for (int i = 0; i < 4; ++i)
#pragma unroll
        for (int j = 0; j < 8; ++j)
#pragma unroll
            for (int k = 0; k < 4; ++k) acc[i][j][k] = 0.0f;

    auto loadA = [&](int kt, int s) {
        const __half* Ag = g_h + (size_t)bm * K + kt * BK;
#pragma unroll
        for (int p = 0; p < 4; ++p) {
            int c = tid + p * 128;
            int row = c >> 2, col = (c & 3) * 8;
            cp_async16(smem_u32(&As[s * A_STAGE + row * SA + col]),
                       Ag + (size_t)row * K + col);
        }
    };
    auto loadB = [&](int kt, int s) {
        const __half* Bg = g_wout + (size_t)(kt * BK) * M + bn;
#pragma unroll
        for (int p = 0; p < 4; ++p) {
            int c = tid + p * 128;
            int row = c >> 4, col = (c & 15) * 8;
            cp_async16(smem_u32(&Bs[s * B_STAGE + row * SB + col]),
                       Bg + (size_t)row * M + col);
        }
    };

#pragma unroll
    for (int s = 0; s < S; ++s) { loadA(s, s); loadB(s, s); cp_commit(); }

    for (int kt = 0; kt < KT; ++kt) {
        const int s = kt % S;
        cp_wait<S - 1>();
        __syncthreads();

#pragma unroll
        for (int ks = 0; ks < 2; ++ks) {
            const int k0 = ks * 16;
            uint32_t afr[4][4];
#pragma unroll
            for (int mi = 0; mi < 4; ++mi) {
                uint32_t addr = smem_u32(
                    &As[s * A_STAGE + (wm * 64 + mi * 16 + (lane & 15)) * SA + k0 + (lane >> 4) * 8]);
                ldsm_x4(addr, afr[mi][0], afr[mi][1], afr[mi][2], afr[mi][3]);
            }
#pragma unroll
            for (int np = 0; np < 4; ++np) {
                uint32_t b0, b1, b2, b3;
                uint32_t addr = smem_u32(
                    &Bs[s * B_STAGE + (k0 + (lane & 15)) * SB + wn * 64 + np * 16 + (lane >> 4) * 8]);
                ldsm_x4_t(addr, b0, b1, b2, b3);
#pragma unroll
                for (int mi = 0; mi < 4; ++mi) {
                    mma16816(acc[mi][np * 2],     afr[mi], b0, b1);
                    mma16816(acc[mi][np * 2 + 1], afr[mi], b2, b3);
                }
            }
        }

        __syncthreads();
        if (kt + S < KT) { loadA(kt + S, s); loadB(kt + S, s); }
        cp_commit();
    }

    // epilogue -> y fp32
    const int row0 = bm + wm * 64;
    const int col0 = wn * 64;
#pragma unroll
    for (int mi = 0; mi < 4; ++mi) {
#pragma unroll
        for (int ni = 0; ni < 8; ++ni) {
            const int r  = row0 + mi * 16 + (lane >> 2);
            const int lc = col0 + ni * 8 + (lane & 3) * 2;
            const int gc = bn + lc;
            const float bb0 = biasS[lc];
            const float bb1 = biasS[lc + 1];
            *reinterpret_cast<float2*>(&y[(size_t)r * M + gc]) =
                make_float2(acc[mi][ni][0] + bb0, acc[mi][ni][1] + bb1);
            *reinterpret_cast<float2*>(&y[(size_t)(r + 8) * M + gc]) =
                make_float2(acc[mi][ni][2] + bb0, acc[mi][ni][3] + bb1);
        }
    }
}

// ---------------------------------------------------------------------------
// kernel_launch. inputs: x, weight_in, weight_out, bias_in, bias_out,
//                        sparse_scale_in, sparse_scale_out
// ---------------------------------------------------------------------------
extern "C" void kernel_launch(void* const* d_in, const int* in_sizes, int n_in,
                              void* d_out, int out_size) {
    const float* x     = (const float*)d_in[0];
    const float* w_in  = (const float*)d_in[1];
    const float* w_out = (const float*)d_in[2];
    const float* b_in  = (const float*)d_in[3];
    const float* b_out = (const float*)d_in[4];
    const float* s_in  = (const float*)d_in[5];
    const float* s_out = (const float*)d_in[6];
    float* y = (float*)d_out;

    constexpr int ngroups = (DDIM * RDIM) / 4;                 // 131072
    prep_both_kernel<<<(2 * ngroups) / 256, 256>>>(w_in, s_in, w_out, s_out);

    constexpr int SMEM0 = 3 * (128 * 40 + 32 * 264) * 2 + 256 * 4;  // 82432
    constexpr int SMEM1 = 3 * (128 * 40 + 32 * 136) * 2 + 128 * 4;  // 57344
    cudaFuncSetAttribute(gemm0_kernel, cudaFuncAttributeMaxDynamicSharedMemorySize, SMEM0);
    cudaFuncSetAttribute(gemm1_kernel, cudaFuncAttributeMaxDynamicSharedMemorySize, SMEM1);

    dim3 g0(1, NTOK / 128);            // 128 CTAs
    gemm0_kernel<<<g0, 256, SMEM0>>>(x, b_in);

    dim3 g1(DDIM / 128, NTOK / 128);   // (16, 128) = 2048 CTAs
    gemm1_kernel<<<g1, 128, SMEM1>>>(b_out, y);
}